// round 15
// baseline (speedup 1.0000x reference)
#include <cuda_runtime.h>
#include <math.h>
#include <stdint.h>

// ---------------------------------------------------------------------------
// ShowAttendTellCore on GB300 (sm_103a).
// Round 15: GEMM1 rebuilt around the smem-crossbar bottleneck found in R14:
// CTA 256x128, 8 warps of 64x64 (MI=4) -> fragment-LDS + fill traffic per
// chunk (1408 crossbar cyc) now fits under the tensor work (2048 cyc).
// ---------------------------------------------------------------------------

#define BATCH   512
#define LSEQ    196
#define DATT    2048
#define HATT    512
#define DRNN    512
#define ROWS    (BATCH * LSEQ)      // 100352
#define NCT     4                   // N tiles of 128 over HATT=512

__device__ float g_atth[BATCH * HATT];
__device__ float g_part[NCT * ROWS];      // per-N-tile partial scores
__device__ float g_scores[ROWS];
__device__ float g_attres[BATCH * DATT];
__device__ float g_gates[BATCH * 4 * DRNN];

// ===================== tf32 mma.sync GEMM common ===========================
#define KC 32
#define NKCH (DATT / KC)           // 64  (GEMM1)
#define SMPAD 36
#define STAGES 3

// GEMM1 smem: 256-row A, 128-row B, 3 stages  (~168 KB, 1 CTA/SM)
struct SmemG1 {
    float As[STAGES][256][SMPAD];
    float Bs[STAGES][128][SMPAD];
    float part[256][2];
};
#define SMEM_G1 (sizeof(SmemG1))

// gates smem: 128-row A and B (~111 KB, as in R14)
struct SmemG2 {
    float As[STAGES][128][SMPAD];
    float Bs[STAGES][128][SMPAD];
};
#define SMEM_G2 (sizeof(SmemG2))

__device__ __forceinline__ uint32_t smem_u32(const void* p) {
    uint32_t a;
    asm("{ .reg .u64 t; cvta.to.shared.u64 t, %1; cvt.u32.u64 %0, t; }"
        : "=r"(a) : "l"(p));
    return a;
}
__device__ __forceinline__ void cp16(uint32_t s, const void* g) {
    asm volatile("cp.async.cg.shared.global [%0], [%1], 16;" :: "r"(s), "l"(g));
}
__device__ __forceinline__ void cp_commit() {
    asm volatile("cp.async.commit_group;" ::: "memory");
}
__device__ __forceinline__ void cp_wait0() {
    asm volatile("cp.async.wait_group 0;" ::: "memory");
}
__device__ __forceinline__ void cp_wait1() {
    asm volatile("cp.async.wait_group 1;" ::: "memory");
}
__device__ __forceinline__ uint32_t f2tf32(float f) {
    uint32_t u;
    asm("cvt.rna.tf32.f32 %0, %1;" : "=r"(u) : "f"(f));
    return u;
}
__device__ __forceinline__ void mma_tf32(float* c, const uint32_t* a,
                                         const uint32_t* b) {
    asm volatile(
        "mma.sync.aligned.m16n8k8.row.col.f32.tf32.tf32.f32 "
        "{%0,%1,%2,%3}, {%4,%5,%6,%7}, {%8,%9}, {%0,%1,%2,%3};"
        : "+f"(c[0]), "+f"(c[1]), "+f"(c[2]), "+f"(c[3])
        : "r"(a[0]), "r"(a[1]), "r"(a[2]), "r"(a[3]), "r"(b[0]), "r"(b[1]));
}

// One chunk (4 k-steps) for a warp tile of (MI*16) x 64.
// RNA=true rounds fragments to tf32 (output path); false = raw fp32 bits.
template <int MI, bool RNA>
__device__ __forceinline__ void mma_chunk(const float (*__restrict__ As)[SMPAD],
                                          const float (*__restrict__ Bs)[SMPAD],
                                          int m0, int n0, int g, int t,
                                          float (*acc)[8][4])
{
    #pragma unroll
    for (int ks = 0; ks < 4; ks++) {
        const int kk = ks * 8;
        uint32_t a[MI][4];
        #pragma unroll
        for (int mi = 0; mi < MI; mi++) {
            const int mb = m0 + mi * 16;
            float a0 = As[mb + g    ][kk + t    ];
            float a1 = As[mb + g + 8][kk + t    ];
            float a2 = As[mb + g    ][kk + t + 4];
            float a3 = As[mb + g + 8][kk + t + 4];
            a[mi][0] = RNA ? f2tf32(a0) : __float_as_uint(a0);
            a[mi][1] = RNA ? f2tf32(a1) : __float_as_uint(a1);
            a[mi][2] = RNA ? f2tf32(a2) : __float_as_uint(a2);
            a[mi][3] = RNA ? f2tf32(a3) : __float_as_uint(a3);
        }
        #pragma unroll
        for (int ni = 0; ni < 8; ni++) {
            const int nb = n0 + ni * 8;
            uint32_t b[2];
            float b0 = Bs[nb + g][kk + t    ];
            float b1 = Bs[nb + g][kk + t + 4];
            b[0] = RNA ? f2tf32(b0) : __float_as_uint(b0);
            b[1] = RNA ? f2tf32(b1) : __float_as_uint(b1);
            #pragma unroll
            for (int mi = 0; mi < MI; mi++)
                mma_tf32(acc[mi][ni], a[mi], b);
        }
    }
}

// ======================= GEMM1 + fused scores ==============================
__device__ __forceinline__ void fill_g1(SmemG1* sm, int s,
                                        const float* __restrict__ Ab,
                                        const float* __restrict__ Bb,
                                        int k0, int tid)
{
    #pragma unroll
    for (int i = 0; i < 12; i++) {          // 3072 16B chunks
        int idx = tid + i * 256;
        if (idx < 2048) {                    // A: 256 rows x 32 k
            int row = idx >> 3, q = (idx & 7) * 4;
            cp16(smem_u32(&sm->As[s][row][q]), Ab + (size_t)row * DATT + k0 + q);
        } else {                             // B: 128 rows x 32 k
            int j = idx - 2048;
            int row = j >> 3, q = (j & 7) * 4;
            cp16(smem_u32(&sm->Bs[s][row][q]), Bb + (size_t)row * DATT + k0 + q);
        }
    }
    cp_commit();
}

// part[ctile][row] = sum_{h in ctile} wal[h]*tanh(att[row,h]+bctx[h]+atth[b,h])
__global__ void __launch_bounds__(256, 1)
att_scores_mma(const float* __restrict__ att_feats,
               const float* __restrict__ W_ctx,
               const float* __restrict__ atth,
               const float* __restrict__ W_alpha,
               const float* __restrict__ b_ctx,
               float* __restrict__ part)
{
    extern __shared__ char smem_raw[];
    SmemG1* sm = (SmemG1*)smem_raw;

    const int tid  = threadIdx.x;
    const int warp = tid >> 5;
    const int lane = tid & 31;
    const int g    = lane >> 2;
    const int t    = lane & 3;
    const int m0   = (warp >> 1) * 64;     // 4 M-warps of 64 rows
    const int wn   = warp & 1;             // 2 N-warps of 64 cols
    const int n0   = wn * 64;

    const int ctile   = blockIdx.x;        // 0..3
    const int rowtile = blockIdx.y;        // 0..391 (256 rows each)
    const float* Ab = att_feats + (size_t)rowtile * 256 * DATT;
    const float* Bb = W_ctx     + (size_t)ctile   * 128 * DATT;

    float acc[4][8][4];
    #pragma unroll
    for (int mi = 0; mi < 4; mi++)
        #pragma unroll
        for (int ni = 0; ni < 8; ni++)
            #pragma unroll
            for (int r = 0; r < 4; r++) acc[mi][ni][r] = 0.f;

    fill_g1(sm, 0, Ab, Bb, 0, tid);
    fill_g1(sm, 1, Ab, Bb, KC, tid);

    // Single-barrier multistage mainloop (invariants as in R14).
    for (int c = 0; c < NKCH; c++) {
        if (c + 1 < NKCH) cp_wait1(); else cp_wait0();
        __syncthreads();
        if (c + 2 < NKCH)
            fill_g1(sm, (c + 2) % STAGES, Ab, Bb, (c + 2) * KC, tid);
        mma_chunk<4, false>(sm->As[c % STAGES], sm->Bs[c % STAGES],
                            m0, n0, g, t, acc);
    }

    // ---- fused epilogue: partial scores over this 128-col tile ----
    float psum[4][2];
    int   bidx[4][2];
    #pragma unroll
    for (int mi = 0; mi < 4; mi++) {
        int r0 = rowtile * 256 + m0 + mi * 16 + g;
        psum[mi][0] = 0.f; psum[mi][1] = 0.f;
        bidx[mi][0] = r0 / LSEQ;
        bidx[mi][1] = (r0 + 8) / LSEQ;
    }
    #pragma unroll
    for (int ni = 0; ni < 8; ni++) {
        const int h0 = ctile * 128 + n0 + ni * 8 + 2 * t;
        const float w0 = __ldg(W_alpha + h0),  w1 = __ldg(W_alpha + h0 + 1);
        const float bc0 = __ldg(b_ctx + h0),   bc1 = __ldg(b_ctx + h0 + 1);
        #pragma unroll
        for (int mi = 0; mi < 4; mi++) {
            const float* ahA = atth + (size_t)bidx[mi][0] * HATT;
            const float* ahB = atth + (size_t)bidx[mi][1] * HATT;
            psum[mi][0] += w0 * tanhf(acc[mi][ni][0] + bc0 + __ldg(ahA + h0));
            psum[mi][0] += w1 * tanhf(acc[mi][ni][1] + bc1 + __ldg(ahA + h0 + 1));
            psum[mi][1] += w0 * tanhf(acc[mi][ni][2] + bc0 + __ldg(ahB + h0));
            psum[mi][1] += w1 * tanhf(acc[mi][ni][3] + bc1 + __ldg(ahB + h0 + 1));
        }
    }
    #pragma unroll
    for (int mi = 0; mi < 4; mi++) {
        #pragma unroll
        for (int hf = 0; hf < 2; hf++) {
            psum[mi][hf] += __shfl_xor_sync(0xffffffffu, psum[mi][hf], 1);
            psum[mi][hf] += __shfl_xor_sync(0xffffffffu, psum[mi][hf], 2);
        }
    }
    if (t == 0) {
        #pragma unroll
        for (int mi = 0; mi < 4; mi++) {
            sm->part[m0 + mi * 16 + g    ][wn] = psum[mi][0];
            sm->part[m0 + mi * 16 + g + 8][wn] = psum[mi][1];
        }
    }
    __syncthreads();
    part[(size_t)ctile * ROWS + rowtile * 256 + tid] =
        sm->part[tid][0] + sm->part[tid][1];
}

// ================= fused gates GEMM (tf32 mma.sync) ========================
// gates[512, 2048] = [xt | attres | h](K=3072) @ [W_ih | W_hh]^T
#define KTOT_G 3072
#define NKCH_G (KTOT_G / KC)       // 96

__device__ __forceinline__ void fill_g2(SmemG2* sm, int s, int k0,
                                        int rowtile, int ctile,
                                        const float* __restrict__ xt,
                                        const float* __restrict__ attres,
                                        const float* __restrict__ h,
                                        const float* __restrict__ W_ih,
                                        const float* __restrict__ W_hh,
                                        int tid)
{
    const float* asrc; int lda;
    if (k0 < 512)       { asrc = xt + k0;              lda = 512;  }
    else if (k0 < 2560) { asrc = attres + (k0 - 512);  lda = 2048; }
    else                { asrc = h + (k0 - 2560);      lda = 512;  }
    asrc += (size_t)rowtile * 128 * lda;

    const float* bsrc; int ldb;
    if (k0 < 2560) { bsrc = W_ih + k0;          ldb = 2560; }
    else           { bsrc = W_hh + (k0 - 2560); ldb = 512;  }
    bsrc += (size_t)ctile * 128 * ldb;

    #pragma unroll
    for (int i = 0; i < 8; i++) {
        int idx = tid + i * 256;
        int row = (idx >> 3) & 127;
        int q   = (idx & 7) * 4;
        if (idx < 1024)
            cp16(smem_u32(&sm->As[s][row][q]), asrc + (size_t)row * lda + q);
        else
            cp16(smem_u32(&sm->Bs[s][row][q]), bsrc + (size_t)row * ldb + q);
    }
    cp_commit();
}

__global__ void __launch_bounds__(256, 2)
gates_mma(const float* __restrict__ xt,
          const float* __restrict__ attres,
          const float* __restrict__ h,
          const float* __restrict__ W_ih,
          const float* __restrict__ W_hh,
          float* __restrict__ gates)
{
    extern __shared__ char smem_raw[];
    SmemG2* sm = (SmemG2*)smem_raw;

    const int tid  = threadIdx.x;
    const int warp = tid >> 5;
    const int lane = tid & 31;
    const int g    = lane >> 2;
    const int t    = lane & 3;
    const int m0   = (warp >> 1) * 32;
    const int n0   = (warp & 1) * 64;

    const int ctile   = blockIdx.x;    // 0..15
    const int rowtile = blockIdx.y;    // 0..3

    float acc[2][8][4];
    #pragma unroll
    for (int mi = 0; mi < 2; mi++)
        #pragma unroll
        for (int ni = 0; ni < 8; ni++)
            #pragma unroll
            for (int r = 0; r < 4; r++) acc[mi][ni][r] = 0.f;

    fill_g2(sm, 0, 0,  rowtile, ctile, xt, attres, h, W_ih, W_hh, tid);
    fill_g2(sm, 1, KC, rowtile, ctile, xt, attres, h, W_ih, W_hh, tid);

    for (int c = 0; c < NKCH_G; c++) {
        if (c + 1 < NKCH_G) cp_wait1(); else cp_wait0();
        __syncthreads();
        if (c + 2 < NKCH_G)
            fill_g2(sm, (c + 2) % STAGES, (c + 2) * KC, rowtile, ctile,
                    xt, attres, h, W_ih, W_hh, tid);
        mma_chunk<2, true>(sm->As[c % STAGES], sm->Bs[c % STAGES],
                           m0, n0, g, t, acc);
    }

    // store 128x128 tile
    const int grow = rowtile * 128 + m0;
    const int gcol = ctile * 128 + n0;
    #pragma unroll
    for (int mi = 0; mi < 2; mi++) {
        #pragma unroll
        for (int ni = 0; ni < 8; ni++) {
            int col = gcol + ni * 8 + 2 * t;
            float* p0 = gates + (size_t)(grow + mi * 16 + g)     * 2048 + col;
            float* p1 = gates + (size_t)(grow + mi * 16 + g + 8) * 2048 + col;
            p0[0] = acc[mi][ni][0]; p0[1] = acc[mi][ni][1];
            p1[0] = acc[mi][ni][2]; p1[1] = acc[mi][ni][3];
        }
    }
}

// ======================= SIMT fp32 GEMM (atth only) ========================
#define BM 128
#define BN 128
#define BK 16

__global__ __launch_bounds__(256, 2)
void gemm_tn(int M, int N, int K,
             const float* __restrict__ A, int lda,
             const float* __restrict__ B, int ldb,
             float* __restrict__ C, int ldc,
             const float* __restrict__ bias)
{
    __shared__ float As[BK][BM];
    __shared__ float Bs[BK][BN];

    const int tid = threadIdx.x;
    const int tx  = tid & 15;
    const int ty  = tid >> 4;

    const float* Ab = A + (size_t)blockIdx.y * BM * lda;
    const float* Bb = B + (size_t)blockIdx.x * BN * ldb;

    float acc[8][8];
    #pragma unroll
    for (int i = 0; i < 8; i++)
        #pragma unroll
        for (int j = 0; j < 8; j++) acc[i][j] = 0.f;

    for (int k0 = 0; k0 < K; k0 += BK) {
        #pragma unroll
        for (int i = 0; i < 2; i++) {
            int idx = tid + i * 256;
            int row = idx >> 2;
            int q   = (idx & 3) << 2;
            float4 va = *(const float4*)(Ab + (size_t)row * lda + k0 + q);
            As[q + 0][row] = va.x; As[q + 1][row] = va.y;
            As[q + 2][row] = va.z; As[q + 3][row] = va.w;
            float4 vb = *(const float4*)(Bb + (size_t)row * ldb + k0 + q);
            Bs[q + 0][row] = vb.x; Bs[q + 1][row] = vb.y;
            Bs[q + 2][row] = vb.z; Bs[q + 3][row] = vb.w;
        }
        __syncthreads();

        #pragma unroll
        for (int k = 0; k < BK; k++) {
            float a[8], b[8];
            *(float4*)&a[0] = *(const float4*)&As[k][ty * 8];
            *(float4*)&a[4] = *(const float4*)&As[k][ty * 8 + 4];
            *(float4*)&b[0] = *(const float4*)&Bs[k][tx * 8];
            *(float4*)&b[4] = *(const float4*)&Bs[k][tx * 8 + 4];
            #pragma unroll
            for (int i = 0; i < 8; i++)
                #pragma unroll
                for (int j = 0; j < 8; j++)
                    acc[i][j] += a[i] * b[j];
        }
        __syncthreads();
    }

    const int row0 = blockIdx.y * BM + ty * 8;
    const int col0 = blockIdx.x * BN + tx * 8;
    #pragma unroll
    for (int i = 0; i < 8; i++) {
        float* Crow = C + (size_t)(row0 + i) * ldc + col0;
        #pragma unroll
        for (int j = 0; j < 8; j++) Crow[j] = acc[i][j] + bias[col0 + j];
    }
}

// ================= softmax over L (fused partial-sum read) =================
__global__ void softmax_kernel(const float* __restrict__ part,
                               float* __restrict__ scores)
{
    __shared__ float red[8];
    int b = blockIdx.x;
    int t = threadIdx.x;

    float v = -1e30f;
    if (t < LSEQ) {
        size_t r = (size_t)b * LSEQ + t;
        v = part[r] + part[ROWS + r] + part[2 * (size_t)ROWS + r]
          + part[3 * (size_t)ROWS + r];
    }
    float m = v;
    #pragma unroll
    for (int o = 16; o; o >>= 1) m = fmaxf(m, __shfl_xor_sync(0xffffffffu, m, o));
    if ((t & 31) == 0) red[t >> 5] = m;
    __syncthreads();
    float bm = red[0];
    #pragma unroll
    for (int i = 1; i < 8; i++) bm = fmaxf(bm, red[i]);

    float e = (t < LSEQ) ? expf(v - bm) : 0.f;
    __syncthreads();
    float ss = e;
    #pragma unroll
    for (int o = 16; o; o >>= 1) ss += __shfl_xor_sync(0xffffffffu, ss, o);
    if ((t & 31) == 0) red[t >> 5] = ss;
    __syncthreads();
    float tot = 0.f;
    #pragma unroll
    for (int i = 0; i < 8; i++) tot += red[i];

    if (t < LSEQ) scores[(size_t)b * LSEQ + t] = e / tot;
}

// ==================== att_res = weights @ att_feats ========================
__global__ void attres_kernel(const float* __restrict__ att_feats,
                              const float* __restrict__ w,
                              float* __restrict__ out)
{
    __shared__ float ws[LSEQ];
    int b  = blockIdx.x >> 1;
    int d4 = ((blockIdx.x & 1) << 8) + threadIdx.x;   // float4 index 0..511
    if (threadIdx.x < LSEQ) ws[threadIdx.x] = w[(size_t)b * LSEQ + threadIdx.x];
    __syncthreads();

    const float4* base = (const float4*)(att_feats + (size_t)b * LSEQ * DATT) + d4;
    float4 acc = make_float4(0.f, 0.f, 0.f, 0.f);
    #pragma unroll 4
    for (int l = 0; l < LSEQ; l++) {
        float4 v = base[(size_t)l * (DATT / 4)];
        float  s = ws[l];
        acc.x += s * v.x; acc.y += s * v.y;
        acc.z += s * v.z; acc.w += s * v.w;
    }
    ((float4*)(out + (size_t)b * DATT))[d4] = acc;
}

// ============================ LSTM elementwise =============================
__device__ __forceinline__ float sigf(float x) { return 1.f / (1.f + expf(-x)); }

__global__ void lstm_kernel(const float* __restrict__ gates,
                            const float* __restrict__ c_prev,
                            float* __restrict__ out, int out_size)
{
    int idx = blockIdx.x * blockDim.x + threadIdx.x;
    int b = idx >> 9;
    int j = idx & 511;
    const float* g = gates + (size_t)b * (4 * DRNN);
    float i_ = sigf(g[j]);
    float f_ = sigf(g[DRNN + j]);
    float gg = tanhf(g[2 * DRNN + j]);
    float o_ = sigf(g[3 * DRNN + j]);
    float cn = f_ * c_prev[idx] + i_ * gg;
    float hn = o_ * tanhf(cn);

    out[idx] = hn;
    if (out_size >= 2 * BATCH * DRNN) out[BATCH * DRNN + idx] = hn;
    if (out_size >= 3 * BATCH * DRNN) out[2 * BATCH * DRNN + idx] = cn;
}

// ---------------------------------------------------------------------------
extern "C" void kernel_launch(void* const* d_in, const int* in_sizes, int n_in,
                              void* d_out, int out_size)
{
    const float* xt        = (const float*)d_in[0];
    const float* att_feats = (const float*)d_in[2];
    const float* h         = (const float*)d_in[3];
    const float* c         = (const float*)d_in[4];
    const float* W_ctx     = (const float*)d_in[5];
    const float* b_ctx     = (const float*)d_in[6];
    const float* W_h2att   = (const float*)d_in[7];
    const float* b_h2att   = (const float*)d_in[8];
    const float* W_alpha   = (const float*)d_in[9];
    const float* W_ih      = (const float*)d_in[11];
    const float* W_hh      = (const float*)d_in[12];
    float* out = (float*)d_out;

    float *atth, *part, *scores, *attres, *gates;
    cudaGetSymbolAddress((void**)&atth,   g_atth);
    cudaGetSymbolAddress((void**)&part,   g_part);
    cudaGetSymbolAddress((void**)&scores, g_scores);
    cudaGetSymbolAddress((void**)&attres, g_attres);
    cudaGetSymbolAddress((void**)&gates,  g_gates);

    cudaFuncSetAttribute(att_scores_mma,
                         cudaFuncAttributeMaxDynamicSharedMemorySize, SMEM_G1);
    cudaFuncSetAttribute(gates_mma,
                         cudaFuncAttributeMaxDynamicSharedMemorySize, SMEM_G2);

    // att_h = h_last @ W_h2att^T + b_h2att           [512,512]
    gemm_tn<<<dim3(HATT / BN, BATCH / BM), 256>>>(
        BATCH, HATT, DRNN, h, DRNN, W_h2att, DRNN, atth, HATT, b_h2att);

    // fused GEMM1 (tf32 mma.sync, 256x128 CTA, 64x64 warps) + scores partials
    att_scores_mma<<<dim3(NCT, ROWS / 256), 256, SMEM_G1>>>(
        att_feats, W_ctx, atth, W_alpha, b_ctx, part);

    // softmax over L per batch row (sums the 4 partials)
    softmax_kernel<<<BATCH, 256>>>(part, scores);

    // att_res = weights @ att_feats                  [512,2048]
    attres_kernel<<<BATCH * 2, 256>>>(att_feats, scores, attres);

    // fused gates GEMM: [xt|attres|h] @ [W_ih|W_hh]^T  (tf32 mma.sync, rna)
    gates_mma<<<dim3(16, 4), 256, SMEM_G2>>>(
        xt, attres, h, W_ih, W_hh, gates);

    // LSTM elementwise + output writes
    lstm_kernel<<<(BATCH * DRNN) / 256, 256>>>(gates, c, out, out_size);
}

// round 17
// speedup vs baseline: 1.4669x; 1.4669x over previous
#include <cuda_runtime.h>
#include <cuda_fp16.h>
#include <math.h>
#include <stdint.h>

// ---------------------------------------------------------------------------
// ShowAttendTellCore on GB300 (sm_103a).
// Round 17: R16 fp16 GEMM1 with the smem-row-stride bug fixed
// (SMPAD_H 40 -> 72 halves; rows store KC_H=64 halves = 128 B).
// 3-stage single-barrier pipeline (R14-proven), 2 CTAs/SM.
// ---------------------------------------------------------------------------

#define BATCH   512
#define LSEQ    196
#define DATT    2048
#define HATT    512
#define DRNN    512
#define ROWS    (BATCH * LSEQ)      // 100352
#define NCT     4                   // N tiles of 128 over HATT=512

__device__ __half g_att_h[(size_t)ROWS * DATT];   // fp16 att_feats (411 MB)
__device__ __half g_wctx_h[HATT * DATT];          // fp16 W_ctx
__device__ float  g_atth[BATCH * HATT];
__device__ float  g_part[NCT * ROWS];             // per-N-tile partial scores
__device__ float  g_scores[ROWS];
__device__ float  g_attres[BATCH * DATT];
__device__ float  g_gates[BATCH * 4 * DRNN];

// ============================ common helpers ===============================
__device__ __forceinline__ uint32_t smem_u32(const void* p) {
    uint32_t a;
    asm("{ .reg .u64 t; cvta.to.shared.u64 t, %1; cvt.u32.u64 %0, t; }"
        : "=r"(a) : "l"(p));
    return a;
}
__device__ __forceinline__ void cp16(uint32_t s, const void* g) {
    asm volatile("cp.async.cg.shared.global [%0], [%1], 16;" :: "r"(s), "l"(g));
}
__device__ __forceinline__ void cp_commit() {
    asm volatile("cp.async.commit_group;" ::: "memory");
}
__device__ __forceinline__ void cp_wait0() {
    asm volatile("cp.async.wait_group 0;" ::: "memory");
}
__device__ __forceinline__ void cp_wait1() {
    asm volatile("cp.async.wait_group 1;" ::: "memory");
}
__device__ __forceinline__ uint32_t f2tf32(float f) {
    uint32_t u;
    asm("cvt.rna.tf32.f32 %0, %1;" : "=r"(u) : "f"(f));
    return u;
}
__device__ __forceinline__ void mma_tf32(float* c, const uint32_t* a,
                                         const uint32_t* b) {
    asm volatile(
        "mma.sync.aligned.m16n8k8.row.col.f32.tf32.tf32.f32 "
        "{%0,%1,%2,%3}, {%4,%5,%6,%7}, {%8,%9}, {%0,%1,%2,%3};"
        : "+f"(c[0]), "+f"(c[1]), "+f"(c[2]), "+f"(c[3])
        : "r"(a[0]), "r"(a[1]), "r"(a[2]), "r"(a[3]), "r"(b[0]), "r"(b[1]));
}
__device__ __forceinline__ void mma_f16(float* c, const uint32_t* a,
                                        const uint32_t* b) {
    asm volatile(
        "mma.sync.aligned.m16n8k16.row.col.f32.f16.f16.f32 "
        "{%0,%1,%2,%3}, {%4,%5,%6,%7}, {%8,%9}, {%0,%1,%2,%3};"
        : "+f"(c[0]), "+f"(c[1]), "+f"(c[2]), "+f"(c[3])
        : "r"(a[0]), "r"(a[1]), "r"(a[2]), "r"(a[3]), "r"(b[0]), "r"(b[1]));
}

// ====================== fp32 -> fp16 conversion ============================
__global__ void f32_to_f16(const float4* __restrict__ in,
                           uint2* __restrict__ out, size_t n4)
{
    size_t i = (size_t)blockIdx.x * blockDim.x + threadIdx.x;
    if (i >= n4) return;
    float4 v = in[i];
    __half2 lo = __floats2half2_rn(v.x, v.y);
    __half2 hi = __floats2half2_rn(v.z, v.w);
    uint2 r;
    r.x = *(const uint32_t*)&lo;
    r.y = *(const uint32_t*)&hi;
    out[i] = r;
}

// =================== GEMM1 (fp16 mma) + fused scores =======================
// CTA 128(M) x 128(N), 8 warps (4M x 2N, each 32x64). KC_H = 64 halves =
// 4 k-steps of m16n8k16. 3-stage cp.async ring, single-barrier loop.
// Row stride 72 halves = 144 B: holds the 64-half chunk (128 B) + pad.
// Fragment LDS bank = (36g + t) mod 32 -> all 32 distinct, conflict-free.
#define KC_H    64
#define NKCH_H  (DATT / KC_H)      // 32
#define SMPAD_H 72
#define STAGES_H 3

struct SmemH {
    __half As[STAGES_H][128][SMPAD_H];
    __half Bs[STAGES_H][128][SMPAD_H];
    float  part[128][2];
};
#define SMEM_H (sizeof(SmemH))      // ~111.6 KB -> 2 CTAs/SM

__device__ __forceinline__ void fill_h(SmemH* sm, int s,
                                       const __half* __restrict__ Ab,
                                       const __half* __restrict__ Bb,
                                       int k0, int tid)
{
    #pragma unroll
    for (int i = 0; i < 8; i++) {           // 2048 16B chunks (8 halves each)
        int idx = tid + i * 256;
        int row = (idx >> 3) & 127;
        int q   = (idx & 7) * 8;            // half offset 0..56 (<= 72-8)
        if (idx < 1024)
            cp16(smem_u32(&sm->As[s][row][q]), Ab + (size_t)row * DATT + k0 + q);
        else
            cp16(smem_u32(&sm->Bs[s][row][q]), Bb + (size_t)row * DATT + k0 + q);
    }
    cp_commit();
}

// part[ctile][row] = sum_{h in ctile} wal[h]*tanh(att[row,h]+bctx[h]+atth[b,h])
__global__ void __launch_bounds__(256, 2)
att_scores_mma(const __half* __restrict__ att_h,
               const __half* __restrict__ wctx_h,
               const float* __restrict__ atth,
               const float* __restrict__ W_alpha,
               const float* __restrict__ b_ctx,
               float* __restrict__ part)
{
    extern __shared__ char smem_raw[];
    SmemH* sm = (SmemH*)smem_raw;

    const int tid  = threadIdx.x;
    const int warp = tid >> 5;
    const int lane = tid & 31;
    const int g    = lane >> 2;
    const int t    = lane & 3;
    const int m0   = (warp >> 1) * 32;
    const int wn   = warp & 1;
    const int n0   = wn * 64;

    const int ctile   = blockIdx.x;        // 0..3
    const int rowtile = blockIdx.y;        // 0..783
    const __half* Ab = att_h  + (size_t)rowtile * 128 * DATT;
    const __half* Bb = wctx_h + (size_t)ctile   * 128 * DATT;

    float acc[2][8][4];
    #pragma unroll
    for (int mi = 0; mi < 2; mi++)
        #pragma unroll
        for (int ni = 0; ni < 8; ni++)
            #pragma unroll
            for (int r = 0; r < 4; r++) acc[mi][ni][r] = 0.f;

    fill_h(sm, 0, Ab, Bb, 0, tid);
    fill_h(sm, 1, Ab, Bb, KC_H, tid);

    // Single-barrier 3-stage mainloop (R14 invariants): barrier at iter c
    // guarantees stage (c-1)%3 consumed -> fill chunk c+2 there; wait_group
    // keeps chunk c complete before compute.
    for (int c = 0; c < NKCH_H; c++) {
        if (c + 1 < NKCH_H) cp_wait1(); else cp_wait0();
        __syncthreads();
        if (c + 2 < NKCH_H)
            fill_h(sm, (c + 2) % STAGES_H, Ab, Bb, (c + 2) * KC_H, tid);

        const __half (*As)[SMPAD_H] = sm->As[c % STAGES_H];
        const __half (*Bs)[SMPAD_H] = sm->Bs[c % STAGES_H];
        #pragma unroll
        for (int ks = 0; ks < 4; ks++) {
            const int kk = ks * 16;
            uint32_t a[2][4];
            #pragma unroll
            for (int mi = 0; mi < 2; mi++) {
                const int mb = m0 + mi * 16;
                a[mi][0] = *(const uint32_t*)&As[mb + g    ][kk + 2 * t    ];
                a[mi][1] = *(const uint32_t*)&As[mb + g + 8][kk + 2 * t    ];
                a[mi][2] = *(const uint32_t*)&As[mb + g    ][kk + 2 * t + 8];
                a[mi][3] = *(const uint32_t*)&As[mb + g + 8][kk + 2 * t + 8];
            }
            #pragma unroll
            for (int ni = 0; ni < 8; ni++) {
                const int nb = n0 + ni * 8;
                uint32_t b[2];
                b[0] = *(const uint32_t*)&Bs[nb + g][kk + 2 * t    ];
                b[1] = *(const uint32_t*)&Bs[nb + g][kk + 2 * t + 8];
                mma_f16(acc[0][ni], a[0], b);
                mma_f16(acc[1][ni], a[1], b);
            }
        }
    }

    // ---- fused epilogue: partial scores over this 128-col tile ----
    float psum[4] = {0.f, 0.f, 0.f, 0.f};
    int   bidx[4];
    #pragma unroll
    for (int mi = 0; mi < 2; mi++) {
        int r0 = rowtile * 128 + m0 + mi * 16 + g;
        bidx[mi * 2 + 0] = r0 / LSEQ;
        bidx[mi * 2 + 1] = (r0 + 8) / LSEQ;
    }
    #pragma unroll
    for (int ni = 0; ni < 8; ni++) {
        const int h0 = ctile * 128 + n0 + ni * 8 + 2 * t;
        const float w0 = __ldg(W_alpha + h0),  w1 = __ldg(W_alpha + h0 + 1);
        const float bc0 = __ldg(b_ctx + h0),   bc1 = __ldg(b_ctx + h0 + 1);
        #pragma unroll
        for (int mi = 0; mi < 2; mi++) {
            const float* ahA = atth + (size_t)bidx[mi * 2 + 0] * HATT;
            const float* ahB = atth + (size_t)bidx[mi * 2 + 1] * HATT;
            psum[mi * 2 + 0] += w0 * tanhf(acc[mi][ni][0] + bc0 + __ldg(ahA + h0));
            psum[mi * 2 + 0] += w1 * tanhf(acc[mi][ni][1] + bc1 + __ldg(ahA + h0 + 1));
            psum[mi * 2 + 1] += w0 * tanhf(acc[mi][ni][2] + bc0 + __ldg(ahB + h0));
            psum[mi * 2 + 1] += w1 * tanhf(acc[mi][ni][3] + bc1 + __ldg(ahB + h0 + 1));
        }
    }
    #pragma unroll
    for (int p = 0; p < 4; p++) {
        psum[p] += __shfl_xor_sync(0xffffffffu, psum[p], 1);
        psum[p] += __shfl_xor_sync(0xffffffffu, psum[p], 2);
    }
    __syncthreads();
    if (t == 0) {
        #pragma unroll
        for (int mi = 0; mi < 2; mi++) {
            sm->part[m0 + mi * 16 + g    ][wn] = psum[mi * 2 + 0];
            sm->part[m0 + mi * 16 + g + 8][wn] = psum[mi * 2 + 1];
        }
    }
    __syncthreads();
    if (tid < 128) {
        part[(size_t)ctile * ROWS + rowtile * 128 + tid] =
            sm->part[tid][0] + sm->part[tid][1];
    }
}

// ================= fused gates GEMM (tf32 mma.sync, R14) ===================
#define KC 32
#define SMPAD 36
#define STAGES 3
#define KTOT_G 3072
#define NKCH_G (KTOT_G / KC)       // 96

struct SmemG2 {
    float As[STAGES][128][SMPAD];
    float Bs[STAGES][128][SMPAD];
};
#define SMEM_G2 (sizeof(SmemG2))

__device__ __forceinline__ void fill_g2(SmemG2* sm, int s, int k0,
                                        int rowtile, int ctile,
                                        const float* __restrict__ xt,
                                        const float* __restrict__ attres,
                                        const float* __restrict__ h,
                                        const float* __restrict__ W_ih,
                                        const float* __restrict__ W_hh,
                                        int tid)
{
    const float* asrc; int lda;
    if (k0 < 512)       { asrc = xt + k0;              lda = 512;  }
    else if (k0 < 2560) { asrc = attres + (k0 - 512);  lda = 2048; }
    else                { asrc = h + (k0 - 2560);      lda = 512;  }
    asrc += (size_t)rowtile * 128 * lda;

    const float* bsrc; int ldb;
    if (k0 < 2560) { bsrc = W_ih + k0;          ldb = 2560; }
    else           { bsrc = W_hh + (k0 - 2560); ldb = 512;  }
    bsrc += (size_t)ctile * 128 * ldb;

    #pragma unroll
    for (int i = 0; i < 8; i++) {
        int idx = tid + i * 256;
        int row = (idx >> 3) & 127;
        int q   = (idx & 7) * 4;
        if (idx < 1024)
            cp16(smem_u32(&sm->As[s][row][q]), asrc + (size_t)row * lda + q);
        else
            cp16(smem_u32(&sm->Bs[s][row][q]), bsrc + (size_t)row * ldb + q);
    }
    cp_commit();
}

__global__ void __launch_bounds__(256, 2)
gates_mma(const float* __restrict__ xt,
          const float* __restrict__ attres,
          const float* __restrict__ h,
          const float* __restrict__ W_ih,
          const float* __restrict__ W_hh,
          float* __restrict__ gates)
{
    extern __shared__ char smem_raw[];
    SmemG2* sm = (SmemG2*)smem_raw;

    const int tid  = threadIdx.x;
    const int warp = tid >> 5;
    const int lane = tid & 31;
    const int g    = lane >> 2;
    const int t    = lane & 3;
    const int m0   = (warp >> 1) * 32;
    const int n0   = (warp & 1) * 64;

    const int ctile   = blockIdx.x;    // 0..15
    const int rowtile = blockIdx.y;    // 0..3

    float acc[2][8][4];
    #pragma unroll
    for (int mi = 0; mi < 2; mi++)
        #pragma unroll
        for (int ni = 0; ni < 8; ni++)
            #pragma unroll
            for (int r = 0; r < 4; r++) acc[mi][ni][r] = 0.f;

    fill_g2(sm, 0, 0,  rowtile, ctile, xt, attres, h, W_ih, W_hh, tid);
    fill_g2(sm, 1, KC, rowtile, ctile, xt, attres, h, W_ih, W_hh, tid);

    for (int c = 0; c < NKCH_G; c++) {
        if (c + 1 < NKCH_G) cp_wait1(); else cp_wait0();
        __syncthreads();
        if (c + 2 < NKCH_G)
            fill_g2(sm, (c + 2) % STAGES, (c + 2) * KC, rowtile, ctile,
                    xt, attres, h, W_ih, W_hh, tid);

        const float (*As)[SMPAD] = sm->As[c % STAGES];
        const float (*Bs)[SMPAD] = sm->Bs[c % STAGES];
        #pragma unroll
        for (int ks = 0; ks < 4; ks++) {
            const int kk = ks * 8;
            uint32_t a[2][4];
            #pragma unroll
            for (int mi = 0; mi < 2; mi++) {
                const int mb = m0 + mi * 16;
                a[mi][0] = f2tf32(As[mb + g    ][kk + t    ]);
                a[mi][1] = f2tf32(As[mb + g + 8][kk + t    ]);
                a[mi][2] = f2tf32(As[mb + g    ][kk + t + 4]);
                a[mi][3] = f2tf32(As[mb + g + 8][kk + t + 4]);
            }
            #pragma unroll
            for (int ni = 0; ni < 8; ni++) {
                const int nb = n0 + ni * 8;
                uint32_t b[2];
                b[0] = f2tf32(Bs[nb + g][kk + t    ]);
                b[1] = f2tf32(Bs[nb + g][kk + t + 4]);
                mma_tf32(acc[0][ni], a[0], b);
                mma_tf32(acc[1][ni], a[1], b);
            }
        }
    }

    const int grow = rowtile * 128 + m0;
    const int gcol = ctile * 128 + n0;
    #pragma unroll
    for (int mi = 0; mi < 2; mi++) {
        #pragma unroll
        for (int ni = 0; ni < 8; ni++) {
            int col = gcol + ni * 8 + 2 * t;
            float* p0 = gates + (size_t)(grow + mi * 16 + g)     * 2048 + col;
            float* p1 = gates + (size_t)(grow + mi * 16 + g + 8) * 2048 + col;
            p0[0] = acc[mi][ni][0]; p0[1] = acc[mi][ni][1];
            p1[0] = acc[mi][ni][2]; p1[1] = acc[mi][ni][3];
        }
    }
}

// ======================= SIMT fp32 GEMM (atth only) ========================
#define BM 128
#define BN 128
#define BK 16

__global__ __launch_bounds__(256, 2)
void gemm_tn(int M, int N, int K,
             const float* __restrict__ A, int lda,
             const float* __restrict__ B, int ldb,
             float* __restrict__ C, int ldc,
             const float* __restrict__ bias)
{
    __shared__ float As[BK][BM];
    __shared__ float Bs[BK][BN];

    const int tid = threadIdx.x;
    const int tx  = tid & 15;
    const int ty  = tid >> 4;

    const float* Ab = A + (size_t)blockIdx.y * BM * lda;
    const float* Bb = B + (size_t)blockIdx.x * BN * ldb;

    float acc[8][8];
    #pragma unroll
    for (int i = 0; i < 8; i++)
        #pragma unroll
        for (int j = 0; j < 8; j++) acc[i][j] = 0.f;

    for (int k0 = 0; k0 < K; k0 += BK) {
        #pragma unroll
        for (int i = 0; i < 2; i++) {
            int idx = tid + i * 256;
            int row = idx >> 2;
            int q   = (idx & 3) << 2;
            float4 va = *(const float4*)(Ab + (size_t)row * lda + k0 + q);
            As[q + 0][row] = va.x; As[q + 1][row] = va.y;
            As[q + 2][row] = va.z; As[q + 3][row] = va.w;
            float4 vb = *(const float4*)(Bb + (size_t)row * ldb + k0 + q);
            Bs[q + 0][row] = vb.x; Bs[q + 1][row] = vb.y;
            Bs[q + 2][row] = vb.z; Bs[q + 3][row] = vb.w;
        }
        __syncthreads();

        #pragma unroll
        for (int k = 0; k < BK; k++) {
            float a[8], b[8];
            *(float4*)&a[0] = *(const float4*)&As[k][ty * 8];
            *(float4*)&a[4] = *(const float4*)&As[k][ty * 8 + 4];
            *(float4*)&b[0] = *(const float4*)&Bs[k][tx * 8];
            *(float4*)&b[4] = *(const float4*)&Bs[k][tx * 8 + 4];
            #pragma unroll
            for (int i = 0; i < 8; i++)
                #pragma unroll
                for (int j = 0; j < 8; j++)
                    acc[i][j] += a[i] * b[j];
        }
        __syncthreads();
    }

    const int row0 = blockIdx.y * BM + ty * 8;
    const int col0 = blockIdx.x * BN + tx * 8;
    #pragma unroll
    for (int i = 0; i < 8; i++) {
        float* Crow = C + (size_t)(row0 + i) * ldc + col0;
        #pragma unroll
        for (int j = 0; j < 8; j++) Crow[j] = acc[i][j] + bias[col0 + j];
    }
}

// ================= softmax over L (fused partial-sum read) =================
__global__ void softmax_kernel(const float* __restrict__ part,
                               float* __restrict__ scores)
{
    __shared__ float red[8];
    int b = blockIdx.x;
    int t = threadIdx.x;

    float v = -1e30f;
    if (t < LSEQ) {
        size_t r = (size_t)b * LSEQ + t;
        v = part[r] + part[ROWS + r] + part[2 * (size_t)ROWS + r]
          + part[3 * (size_t)ROWS + r];
    }
    float m = v;
    #pragma unroll
    for (int o = 16; o; o >>= 1) m = fmaxf(m, __shfl_xor_sync(0xffffffffu, m, o));
    if ((t & 31) == 0) red[t >> 5] = m;
    __syncthreads();
    float bm = red[0];
    #pragma unroll
    for (int i = 1; i < 8; i++) bm = fmaxf(bm, red[i]);

    float e = (t < LSEQ) ? expf(v - bm) : 0.f;
    __syncthreads();
    float ss = e;
    #pragma unroll
    for (int o = 16; o; o >>= 1) ss += __shfl_xor_sync(0xffffffffu, ss, o);
    if ((t & 31) == 0) red[t >> 5] = ss;
    __syncthreads();
    float tot = 0.f;
    #pragma unroll
    for (int i = 0; i < 8; i++) tot += red[i];

    if (t < LSEQ) scores[(size_t)b * LSEQ + t] = e / tot;
}

// ============== att_res = weights @ att_feats (fp16 source) ================
__global__ void attres_kernel(const __half* __restrict__ att_h,
                              const float* __restrict__ w,
                              float* __restrict__ out)
{
    __shared__ float ws[LSEQ];
    int b = blockIdx.x;
    int tid = threadIdx.x;
    if (tid < LSEQ) ws[tid] = w[(size_t)b * LSEQ + tid];
    __syncthreads();

    const uint4* base = (const uint4*)(att_h + (size_t)b * LSEQ * DATT) + tid;
    float acc[8] = {0.f, 0.f, 0.f, 0.f, 0.f, 0.f, 0.f, 0.f};
    #pragma unroll 4
    for (int l = 0; l < LSEQ; l++) {
        uint4 v = base[(size_t)l * (DATT / 8)];
        float s = ws[l];
        float2 f0 = __half22float2(*(const __half2*)&v.x);
        float2 f1 = __half22float2(*(const __half2*)&v.y);
        float2 f2 = __half22float2(*(const __half2*)&v.z);
        float2 f3 = __half22float2(*(const __half2*)&v.w);
        acc[0] += s * f0.x; acc[1] += s * f0.y;
        acc[2] += s * f1.x; acc[3] += s * f1.y;
        acc[4] += s * f2.x; acc[5] += s * f2.y;
        acc[6] += s * f3.x; acc[7] += s * f3.y;
    }
    float4* o = (float4*)(out + (size_t)b * DATT) + tid * 2;
    o[0] = make_float4(acc[0], acc[1], acc[2], acc[3]);
    o[1] = make_float4(acc[4], acc[5], acc[6], acc[7]);
}

// ============================ LSTM elementwise =============================
__device__ __forceinline__ float sigf(float x) { return 1.f / (1.f + expf(-x)); }

__global__ void lstm_kernel(const float* __restrict__ gates,
                            const float* __restrict__ c_prev,
                            float* __restrict__ out, int out_size)
{
    int idx = blockIdx.x * blockDim.x + threadIdx.x;
    int b = idx >> 9;
    int j = idx & 511;
    const float* g = gates + (size_t)b * (4 * DRNN);
    float i_ = sigf(g[j]);
    float f_ = sigf(g[DRNN + j]);
    float gg = tanhf(g[2 * DRNN + j]);
    float o_ = sigf(g[3 * DRNN + j]);
    float cn = f_ * c_prev[idx] + i_ * gg;
    float hn = o_ * tanhf(cn);

    out[idx] = hn;
    if (out_size >= 2 * BATCH * DRNN) out[BATCH * DRNN + idx] = hn;
    if (out_size >= 3 * BATCH * DRNN) out[2 * BATCH * DRNN + idx] = cn;
}

// ---------------------------------------------------------------------------
extern "C" void kernel_launch(void* const* d_in, const int* in_sizes, int n_in,
                              void* d_out, int out_size)
{
    const float* xt        = (const float*)d_in[0];
    const float* att_feats = (const float*)d_in[2];
    const float* h         = (const float*)d_in[3];
    const float* c         = (const float*)d_in[4];
    const float* W_ctx     = (const float*)d_in[5];
    const float* b_ctx     = (const float*)d_in[6];
    const float* W_h2att   = (const float*)d_in[7];
    const float* b_h2att   = (const float*)d_in[8];
    const float* W_alpha   = (const float*)d_in[9];
    const float* W_ih      = (const float*)d_in[11];
    const float* W_hh      = (const float*)d_in[12];
    float* out = (float*)d_out;

    __half *att_h, *wctx_h;
    float *atth, *part, *scores, *attres, *gates;
    cudaGetSymbolAddress((void**)&att_h,  g_att_h);
    cudaGetSymbolAddress((void**)&wctx_h, g_wctx_h);
    cudaGetSymbolAddress((void**)&atth,   g_atth);
    cudaGetSymbolAddress((void**)&part,   g_part);
    cudaGetSymbolAddress((void**)&scores, g_scores);
    cudaGetSymbolAddress((void**)&attres, g_attres);
    cudaGetSymbolAddress((void**)&gates,  g_gates);

    cudaFuncSetAttribute(att_scores_mma,
                         cudaFuncAttributeMaxDynamicSharedMemorySize, SMEM_H);
    cudaFuncSetAttribute(gates_mma,
                         cudaFuncAttributeMaxDynamicSharedMemorySize, SMEM_G2);

    // fp32 -> fp16 conversion of att_feats and W_ctx
    {
        size_t n4a = (size_t)ROWS * DATT / 4;
        f32_to_f16<<<(unsigned)(n4a / 256), 256>>>(
            (const float4*)att_feats, (uint2*)att_h, n4a);
        size_t n4w = (size_t)HATT * DATT / 4;
        f32_to_f16<<<(unsigned)((n4w + 255) / 256), 256>>>(
            (const float4*)W_ctx, (uint2*)wctx_h, n4w);
    }

    // att_h = h_last @ W_h2att^T + b_h2att           [512,512]
    gemm_tn<<<dim3(HATT / BN, BATCH / BM), 256>>>(
        BATCH, HATT, DRNN, h, DRNN, W_h2att, DRNN, atth, HATT, b_h2att);

    // fused GEMM1 (fp16 m16n8k16, 3-stage single-barrier) + scores partials
    att_scores_mma<<<dim3(NCT, ROWS / 128), 256, SMEM_H>>>(
        att_h, wctx_h, atth, W_alpha, b_ctx, part);

    // softmax over L per batch row (sums the 4 partials)
    softmax_kernel<<<BATCH, 256>>>(part, scores);

    // att_res = weights @ att_feats (fp16 source)    [512,2048]
    attres_kernel<<<BATCH, 256>>>(att_h, scores, attres);

    // fused gates GEMM: [xt|attres|h] @ [W_ih|W_hh]^T  (tf32 mma.sync, rna)
    gates_mma<<<dim3(16, 4), 256, SMEM_G2>>>(
        xt, attres, h, W_ih, W_hh, gates);

    // LSTM elementwise + output writes
    lstm_kernel<<<(BATCH * DRNN) / 256, 256>>>(gates, c, out, out_size);
}